// round 1
// baseline (speedup 1.0000x reference)
#include <cuda_runtime.h>

// ---------------- problem constants ----------------
#define T_TOK 8192
#define H_DIM 2048
#define N_EXP 16
#define K_SEL 4
#define IM    1408
#define ISH   5632
#define TK    (T_TOK*K_SEL)

// ---------------- GEMM tile config ----------------
#define BM 128
#define BN 64
#define BK 16
#define SA_LD (BK+4)   // 20 floats
#define SB_LD (BN+4)   // 68 floats
#define MAX_GTILES 272 // >= sum_e ceil(cnt_e/128) worst case (<=271)

// ---------------- device scratch (no allocs allowed) ----------------
__device__ float g_route_w[TK];
__device__ int   g_route_e[TK];
__device__ int   g_counts[N_EXP];
__device__ int   g_offsets[N_EXP];
__device__ int   g_cursor[N_EXP];
__device__ int   g_tile_off[N_EXP+1];
__device__ int   g_total_tiles;
__device__ int   g_row_token[TK];
__device__ int   g_pos_of[TK];
__device__ float g_gate_s[T_TOK];
__device__ float g_act[(size_t)TK*IM];          // 184 MB
__device__ float g_replica[(size_t)TK*H_DIM];   // 268 MB
__device__ float g_s1[(size_t)T_TOK*ISH];       // 184 MB

// ---------------- helpers ----------------
__device__ __forceinline__ unsigned f2tf(float f){
  unsigned u; asm("cvt.rna.tf32.f32 %0, %1;" : "=r"(u) : "f"(f)); return u;
}
__device__ __forceinline__ void mma8(float* c, const unsigned* a, const unsigned* b){
  asm volatile("mma.sync.aligned.m16n8k8.row.col.f32.tf32.tf32.f32 "
    "{%0,%1,%2,%3}, {%4,%5,%6,%7}, {%8,%9}, {%0,%1,%2,%3};"
    : "+f"(c[0]),"+f"(c[1]),"+f"(c[2]),"+f"(c[3])
    : "r"(a[0]),"r"(a[1]),"r"(a[2]),"r"(a[3]),"r"(b[0]),"r"(b[1]));
}

// ---------------- small kernels ----------------
__global__ void zero_kernel() {
  int i = threadIdx.x;
  if (i < N_EXP) { g_counts[i]=0; g_cursor[i]=0; }
}

// One warp per token: fp32 logits, softmax, top-4, shared sigmoid gate.
__global__ void router_kernel(const float* __restrict__ X,
                              const float* __restrict__ RW,
                              const float* __restrict__ WGE) {
  int warp = threadIdx.x >> 5;
  int lane = threadIdx.x & 31;
  int t = blockIdx.x * 8 + warp;
  if (t >= T_TOK) return;
  const float* x = X + (size_t)t * H_DIM;
  float acc[N_EXP];
  #pragma unroll
  for (int e=0;e<N_EXP;e++) acc[e]=0.f;
  float accg = 0.f;
  // float4 vectorized strided loop
  for (int i4 = lane*4; i4 < H_DIM; i4 += 32*4) {
    float4 xv = *(const float4*)(x + i4);
    #pragma unroll
    for (int e=0;e<N_EXP;e++) {
      float4 wv = *(const float4*)(RW + (size_t)e*H_DIM + i4);
      acc[e] = fmaf(xv.x, wv.x, acc[e]);
      acc[e] = fmaf(xv.y, wv.y, acc[e]);
      acc[e] = fmaf(xv.z, wv.z, acc[e]);
      acc[e] = fmaf(xv.w, wv.w, acc[e]);
    }
    float4 gv = *(const float4*)(WGE + i4);
    accg = fmaf(xv.x, gv.x, accg);
    accg = fmaf(xv.y, gv.y, accg);
    accg = fmaf(xv.z, gv.z, accg);
    accg = fmaf(xv.w, gv.w, accg);
  }
  #pragma unroll
  for (int e=0;e<N_EXP;e++)
    #pragma unroll
    for (int o=16;o>0;o>>=1) acc[e] += __shfl_xor_sync(0xffffffffu, acc[e], o);
  #pragma unroll
  for (int o=16;o>0;o>>=1) accg += __shfl_xor_sync(0xffffffffu, accg, o);
  if (lane==0) {
    float m = acc[0];
    #pragma unroll
    for (int e=1;e<N_EXP;e++) m = fmaxf(m, acc[e]);
    float p[N_EXP]; float s=0.f;
    #pragma unroll
    for (int e=0;e<N_EXP;e++){ p[e]=expf(acc[e]-m); s+=p[e]; }
    float inv = 1.f/s;
    #pragma unroll
    for (int e=0;e<N_EXP;e++) p[e]*=inv;
    for (int k=0;k<K_SEL;k++){
      int be=0; float bv=-1.f;
      #pragma unroll
      for (int e=0;e<N_EXP;e++) if (p[e]>bv){bv=p[e];be=e;}
      g_route_w[t*K_SEL+k]=bv;
      g_route_e[t*K_SEL+k]=be;
      atomicAdd(&g_counts[be],1);
      p[be]=-2.f;
    }
    g_gate_s[t] = 1.f/(1.f+expf(-accg));
  }
}

__global__ void scan_kernel() {
  if (threadIdx.x==0 && blockIdx.x==0) {
    int run=0, trun=0;
    for (int e=0;e<N_EXP;e++){
      g_offsets[e]=run;
      g_tile_off[e]=trun;
      run  += g_counts[e];
      trun += (g_counts[e]+BM-1)/BM;
    }
    g_tile_off[N_EXP]=trun;
    g_total_tiles=trun;
  }
}

__global__ void assign_kernel() {
  int id = blockIdx.x*blockDim.x + threadIdx.x;
  if (id >= TK) return;
  int e = g_route_e[id];
  int p = g_offsets[e] + atomicAdd(&g_cursor[e],1);
  g_row_token[p] = id >> 2;
  g_pos_of[id] = p;
}

// ---------------- unified tf32 tensor-core GEMM ----------------
// C[seg_start+r, n] = A_row(r) . B0[:,n]   (optionally dual-B with SwiGLU epilogue,
// optionally gathered A rows, optionally gated accumulate into out)
// A rows are full-K (lda == Kdim). B is [Kdim x ldb] row-major (+ per-expert stride).
template<bool DUAL, bool GATHER, bool GADD>
__global__ __launch_bounds__(256,2) void gemm_tpl(
    const float* __restrict__ A,
    const float* __restrict__ B0g,
    const float* __restrict__ B1g,
    float* __restrict__ out,
    int Kdim, int ldb, long estride, int ldo,
    int grouped, int denseM,
    const float* __restrict__ gate_vec)
{
  int seg_start, seg, row0, e;
  if (grouped) {
    int w = blockIdx.y;
    if (w >= g_total_tiles) return;
    e = 0;
    while (w >= g_tile_off[e+1]) e++;
    seg_start = g_offsets[e];
    seg       = g_counts[e];
    row0      = (w - g_tile_off[e]) * BM;
  } else {
    e = 0; seg_start = 0; seg = denseM; row0 = blockIdx.y * BM;
  }
  if (row0 >= seg) return;
  int n0 = blockIdx.x * BN;
  const float* B0 = B0g + (size_t)e * estride;
  const float* B1 = nullptr;
  if constexpr (DUAL) B1 = B1g + (size_t)e * estride;

  __shared__ float sA[BM*SA_LD];
  __shared__ float sB0[BK*SB_LD];
  __shared__ float sB1[DUAL ? BK*SB_LD : 1];

  int tid  = threadIdx.x;
  int lane = tid & 31, warp = tid >> 5;
  int wm = warp >> 1;   // 0..3 (rows)
  int wn = warp & 1;    // 0..1 (cols)

  // ---- gmem load assignments ----
  int r0 = tid >> 2;            // 0..63
  int c4 = (tid & 3) << 2;      // 0,4,8,12
  int rA0 = row0 + r0;       if (rA0 >= seg) rA0 = seg-1;
  int rA1 = row0 + r0 + 64;  if (rA1 >= seg) rA1 = seg-1;
  const float *arow0, *arow1;
  if constexpr (GATHER) {
    arow0 = A + (size_t)g_row_token[seg_start + rA0] * Kdim;
    arow1 = A + (size_t)g_row_token[seg_start + rA1] * Kdim;
  } else {
    arow0 = A + (size_t)(seg_start + rA0) * Kdim;
    arow1 = A + (size_t)(seg_start + rA1) * Kdim;
  }
  int bk  = tid >> 4;            // 0..15
  int bn4 = (tid & 15) << 2;     // 0..60
  const float* bp0 = B0 + (size_t)bk * ldb + n0 + bn4;
  const float* bp1 = nullptr;
  if constexpr (DUAL) bp1 = B1 + (size_t)bk * ldb + n0 + bn4;

  float acc0[2][4][4];
  float acc1[2][4][4];
  #pragma unroll
  for (int i=0;i<2;i++)
    #pragma unroll
    for (int j=0;j<4;j++)
      #pragma unroll
      for (int q=0;q<4;q++){ acc0[i][j][q]=0.f; acc1[i][j][q]=0.f; }

  int nk = Kdim / BK;
  for (int kt=0; kt<nk; kt++) {
    int k0 = kt*BK;
    float4 va0 = *(const float4*)(arow0 + k0 + c4);
    float4 va1 = *(const float4*)(arow1 + k0 + c4);
    float4 vb0 = *(const float4*)(bp0 + (size_t)k0 * ldb);
    float4 vb1 = make_float4(0.f,0.f,0.f,0.f);
    if constexpr (DUAL) vb1 = *(const float4*)(bp1 + (size_t)k0 * ldb);
    {
      float4 w;
      w.x=__uint_as_float(f2tf(va0.x)); w.y=__uint_as_float(f2tf(va0.y));
      w.z=__uint_as_float(f2tf(va0.z)); w.w=__uint_as_float(f2tf(va0.w));
      *(float4*)&sA[r0*SA_LD + c4] = w;
      w.x=__uint_as_float(f2tf(va1.x)); w.y=__uint_as_float(f2tf(va1.y));
      w.z=__uint_as_float(f2tf(va1.z)); w.w=__uint_as_float(f2tf(va1.w));
      *(float4*)&sA[(r0+64)*SA_LD + c4] = w;
      w.x=__uint_as_float(f2tf(vb0.x)); w.y=__uint_as_float(f2tf(vb0.y));
      w.z=__uint_as_float(f2tf(vb0.z)); w.w=__uint_as_float(f2tf(vb0.w));
      *(float4*)&sB0[bk*SB_LD + bn4] = w;
      if constexpr (DUAL) {
        w.x=__uint_as_float(f2tf(vb1.x)); w.y=__uint_as_float(f2tf(vb1.y));
        w.z=__uint_as_float(f2tf(vb1.z)); w.w=__uint_as_float(f2tf(vb1.w));
        *(float4*)&sB1[bk*SB_LD + bn4] = w;
      }
    }
    __syncthreads();
    #pragma unroll
    for (int ks=0; ks<2; ks++){
      unsigned afr[2][4];
      #pragma unroll
      for (int mt=0;mt<2;mt++){
        int rr = wm*32 + mt*16 + (lane>>2);
        int cc = ks*8 + (lane&3);
        afr[mt][0] = __float_as_uint(sA[ rr    *SA_LD + cc    ]);
        afr[mt][1] = __float_as_uint(sA[(rr+8) *SA_LD + cc    ]);
        afr[mt][2] = __float_as_uint(sA[ rr    *SA_LD + cc + 4]);
        afr[mt][3] = __float_as_uint(sA[(rr+8) *SA_LD + cc + 4]);
      }
      #pragma unroll
      for (int nt=0;nt<4;nt++){
        int nn = wn*32 + nt*8 + (lane>>2);
        int kk = ks*8 + (lane&3);
        unsigned bfr[2];
        bfr[0] = __float_as_uint(sB0[ kk   *SB_LD + nn]);
        bfr[1] = __float_as_uint(sB0[(kk+4)*SB_LD + nn]);
        #pragma unroll
        for (int mt=0;mt<2;mt++) mma8(acc0[mt][nt], afr[mt], bfr);
        if constexpr (DUAL) {
          unsigned cfr[2];
          cfr[0] = __float_as_uint(sB1[ kk   *SB_LD + nn]);
          cfr[1] = __float_as_uint(sB1[(kk+4)*SB_LD + nn]);
          #pragma unroll
          for (int mt=0;mt<2;mt++) mma8(acc1[mt][nt], afr[mt], cfr);
        }
      }
    }
    __syncthreads();
  }

  // ---- epilogue ----
  #pragma unroll
  for (int mt=0;mt<2;mt++){
    #pragma unroll
    for (int nt=0;nt<4;nt++){
      int rr = wm*32 + mt*16 + (lane>>2);
      int cc = n0 + wn*32 + nt*8 + ((lane&3)<<1);
      #pragma unroll
      for (int half=0; half<2; half++){
        int rloc = row0 + rr + half*8;
        if (rloc < seg) {
          float v0, v1;
          if constexpr (DUAL) {
            float gg0 = acc0[mt][nt][half*2+0], uu0 = acc1[mt][nt][half*2+0];
            float gg1 = acc0[mt][nt][half*2+1], uu1 = acc1[mt][nt][half*2+1];
            v0 = gg0 * (1.f/(1.f+expf(-gg0))) * uu0;
            v1 = gg1 * (1.f/(1.f+expf(-gg1))) * uu1;
          } else {
            v0 = acc0[mt][nt][half*2+0];
            v1 = acc0[mt][nt][half*2+1];
          }
          size_t oidx = (size_t)(seg_start + rloc) * ldo + cc;
          if constexpr (GADD) {
            float gg = gate_vec[seg_start + rloc];
            float2 cur = *(float2*)&out[oidx];
            cur.x += gg*v0; cur.y += gg*v1;
            *(float2*)&out[oidx] = cur;
          } else {
            float2 st; st.x = v0; st.y = v1;
            *(float2*)&out[oidx] = st;
          }
        }
      }
    }
  }
}

// out[t,:] = sum_k w[t,k] * replica[pos[t,k], :]
__global__ void combine_kernel(float* __restrict__ out) {
  int id = blockIdx.x*blockDim.x + threadIdx.x;
  const int HV = H_DIM/4;
  if (id >= T_TOK*HV) return;
  int t  = id / HV;
  int h4 = (id % HV) * 4;
  float4 acc = make_float4(0.f,0.f,0.f,0.f);
  #pragma unroll
  for (int k=0;k<K_SEL;k++){
    float w = g_route_w[t*K_SEL+k];
    int   p = g_pos_of[t*K_SEL+k];
    float4 v = *(const float4*)&g_replica[(size_t)p*H_DIM + h4];
    acc.x = fmaf(w, v.x, acc.x);
    acc.y = fmaf(w, v.y, acc.y);
    acc.z = fmaf(w, v.z, acc.z);
    acc.w = fmaf(w, v.w, acc.w);
  }
  *(float4*)&out[(size_t)t*H_DIM + h4] = acc;
}

// ---------------- launch ----------------
extern "C" void kernel_launch(void* const* d_in, const int* in_sizes, int n_in,
                              void* d_out, int out_size) {
  const float* X   = (const float*)d_in[0];  // [T,H]
  const float* RW  = (const float*)d_in[1];  // [E,H]
  const float* GUW = (const float*)d_in[2];  // [E,H,2*IM]
  const float* DW  = (const float*)d_in[3];  // [E,IM,H]
  const float* SGW = (const float*)d_in[4];  // [H,ISH]
  const float* SUW = (const float*)d_in[5];  // [H,ISH]
  const float* SDW = (const float*)d_in[6];  // [ISH,H]
  const float* WGE = (const float*)d_in[7];  // [H,1]
  float* out = (float*)d_out;

  void *p_act_v, *p_rep_v, *p_s1_v, *p_gate_v;
  cudaGetSymbolAddress(&p_act_v,  g_act);
  cudaGetSymbolAddress(&p_rep_v,  g_replica);
  cudaGetSymbolAddress(&p_s1_v,   g_s1);
  cudaGetSymbolAddress(&p_gate_v, g_gate_s);
  float* p_act  = (float*)p_act_v;
  float* p_rep  = (float*)p_rep_v;
  float* p_s1   = (float*)p_s1_v;
  float* p_gate = (float*)p_gate_v;

  zero_kernel<<<1,32>>>();
  router_kernel<<<T_TOK/8,256>>>(X, RW, WGE);
  scan_kernel<<<1,32>>>();
  assign_kernel<<<TK/256,256>>>();

  // G1: grouped SwiGLU gate_up GEMM (gathered A), act = silu(X@Wg)*(X@Wu)
  gemm_tpl<true,true,false><<<dim3(IM/BN, MAX_GTILES, 1),256>>>(
      X, GUW, GUW + IM, p_act,
      H_DIM, 2*IM, (long)H_DIM*2*IM, IM, 1, 0, nullptr);

  // G2: grouped down GEMM, replica = act @ down_w[e]
  gemm_tpl<false,false,false><<<dim3(H_DIM/BN, MAX_GTILES, 1),256>>>(
      p_act, DW, nullptr, p_rep,
      IM, H_DIM, (long)IM*H_DIM, H_DIM, 1, 0, nullptr);

  // weighted combine -> out
  combine_kernel<<<(T_TOK*(H_DIM/4))/256,256>>>(out);

  // G3: shared SwiGLU GEMM (dense), s1 = silu(X@Wsg)*(X@Wsu)
  gemm_tpl<true,false,false><<<dim3(ISH/BN, T_TOK/BM, 1),256>>>(
      X, SGW, SUW, p_s1,
      H_DIM, ISH, 0, ISH, 0, T_TOK, nullptr);

  // G4: shared down GEMM (dense), out += sigmoid(X@wge) * (s1 @ Wsd)
  gemm_tpl<false,false,true><<<dim3(H_DIM/BN, T_TOK/BM, 1),256>>>(
      p_s1, SDW, nullptr, out,
      ISH, H_DIM, 0, H_DIM, 0, T_TOK, p_gate);
}

// round 13
// speedup vs baseline: 6.8752x; 6.8752x over previous
#include <cuda_runtime.h>
#include <cuda_fp16.h>
#include <cstdint>

// ---------------- problem constants ----------------
#define T_TOK 8192
#define H_DIM 2048
#define N_EXP 16
#define K_SEL 4
#define IM    1408
#define ISH   5632
#define TK    (T_TOK*K_SEL)

#define BM 128
#define BN 128
#define BK2 64          // fp16 elements of K per pipeline stage (=128 bytes)
#define MAX_GTILES 272

// ---- arch-feature dispatch: tcgen05 only exists on sm_10xa / sm_10xf targets ----
#if defined(__CUDA_ARCH_FEAT_SM103_ALL) || defined(__CUDA_ARCH_FEAT_SM100_ALL) || \
    (defined(__CUDA_ARCH_SPECIFIC__) && (__CUDA_ARCH_SPECIFIC__ >= 1000)) || \
    (defined(__CUDA_ARCH_FAMILY_SPECIFIC__) && (__CUDA_ARCH_FAMILY_SPECIFIC__ >= 1000))
#define USE_TC5 1
#else
#define USE_TC5 0
#endif

// ---------------- device scratch ----------------
__device__ float g_route_w[TK];
__device__ int   g_route_e[TK];
__device__ int   g_counts[N_EXP];
__device__ int   g_offsets[N_EXP];
__device__ int   g_cursor[N_EXP];
__device__ int   g_tile_off[N_EXP+1];
__device__ int   g_total_tiles;
__device__ int   g_row_token[TK];
__device__ int   g_pos_of[TK];
__device__ float g_gate_s[T_TOK];
__device__ __half g_x16 [(size_t)T_TOK*H_DIM];
__device__ __half g_guwt[(size_t)N_EXP*2*IM*H_DIM];   // [E][2IM][H]
__device__ __half g_dwt [(size_t)N_EXP*H_DIM*IM];     // [E][H][IM]
__device__ __half g_sgwt[(size_t)ISH*H_DIM];          // [ISH][H]
__device__ __half g_suwt[(size_t)ISH*H_DIM];          // [ISH][H]
__device__ __half g_sdwt[(size_t)H_DIM*ISH];          // [H][ISH]
__device__ __half g_act [(size_t)TK*IM];
__device__ __half g_s1  [(size_t)T_TOK*ISH];
__device__ float  g_replica[(size_t)TK*H_DIM];

// ---------------- PTX helpers ----------------
__device__ __forceinline__ uint32_t smem_to_u32(const void* p){
  uint32_t a;
  asm("{ .reg .u64 t; cvta.to.shared.u64 t, %1; cvt.u32.u64 %0, t; }" : "=r"(a) : "l"(p));
  return a;
}
__device__ __forceinline__ uint32_t elect_one_pred(){
  uint32_t p;
  asm volatile("{ .reg .pred p; elect.sync _|p, 0xFFFFFFFF; selp.b32 %0, 1, 0, p; }" : "=r"(p));
  return p;
}
#define MBARRIER_INIT(addr, cnt) \
  asm volatile("mbarrier.init.shared.b64 [%0], %1;" :: "r"((uint32_t)(addr)), "r"((uint32_t)(cnt)) : "memory")
#define MBARRIER_INVAL(addr) \
  asm volatile("mbarrier.inval.shared.b64 [%0];" :: "r"((uint32_t)(addr)) : "memory")
#define MBARRIER_WAIT_PARITY(mbar_smem_addr, phase_parity) do { \
    uint32_t _mbar = (uint32_t)(mbar_smem_addr); \
    uint32_t _parity = (uint32_t)(phase_parity); \
    uint32_t _done; \
    asm volatile( \
        "{\n\t.reg .pred p;\n\t" \
        "mbarrier.try_wait.parity.acquire.cta.shared::cta.b64 p, [%1], %2;\n\t" \
        "selp.b32 %0, 1, 0, p;\n\t}" \
        : "=r"(_done) : "r"(_mbar), "r"(_parity) : "memory"); \
    if (!_done) { \
        asm volatile( \
            "{\n\t.reg .pred P1;\n\t" \
            "WAIT_LOOP_%=:\n\t" \
            "mbarrier.try_wait.parity.acquire.cta.shared::cta.b64 P1, [%0], %1, 0x989680;\n\t" \
            "@P1 bra.uni WAIT_DONE_%=;\n\t" \
            "bra.uni WAIT_LOOP_%=;\n\t" \
            "WAIT_DONE_%=:\n\t}" \
            :: "r"(_mbar), "r"(_parity) : "memory"); \
    } \
} while(0)

#if USE_TC5
#define TCGEN05_ALLOC(smem_addr, nCols) \
  asm volatile("tcgen05.alloc.cta_group::1.sync.aligned.shared::cta.b32 [%0], %1;" \
               :: "r"((uint32_t)(smem_addr)), "r"((uint32_t)(nCols)) : "memory")
#define TCGEN05_DEALLOC(tmem_addr, nCols) \
  asm volatile("tcgen05.dealloc.cta_group::1.sync.aligned.b32 %0, %1;" \
               :: "r"(tmem_addr), "r"((uint32_t)(nCols)))
#define TCGEN05_RELINQ() \
  asm volatile("tcgen05.relinquish_alloc_permit.cta_group::1.sync.aligned;")
#define TCGEN05_COMMIT(mbar_smem_addr) \
  asm volatile("tcgen05.commit.cta_group::1.mbarrier::arrive::one.shared::cluster.b64 [%0];" \
               :: "r"((uint32_t)(mbar_smem_addr)) : "memory")
#define TCGEN05_FENCE_AFTER() \
  asm volatile("tcgen05.fence::after_thread_sync;" ::: "memory")
#define TCGEN05_FENCE_BEFORE() \
  asm volatile("tcgen05.fence::before_thread_sync;" ::: "memory")
#define TCGEN05_WAIT_LD() \
  asm volatile("tcgen05.wait::ld.sync.aligned;" ::: "memory")
#define TCGEN05_LD_32X32B_X32(r, tmem_addr) \
    asm volatile( \
        "tcgen05.ld.sync.aligned.32x32b.x32.b32 " \
        "{%0, %1, %2, %3, %4, %5, %6, %7, " \
        " %8, %9, %10, %11, %12, %13, %14, %15, " \
        " %16, %17, %18, %19, %20, %21, %22, %23, " \
        " %24, %25, %26, %27, %28, %29, %30, %31}, [%32];" \
        : "=r"((r)[0]),  "=r"((r)[1]),  "=r"((r)[2]),  "=r"((r)[3]), \
          "=r"((r)[4]),  "=r"((r)[5]),  "=r"((r)[6]),  "=r"((r)[7]), \
          "=r"((r)[8]),  "=r"((r)[9]),  "=r"((r)[10]), "=r"((r)[11]), \
          "=r"((r)[12]), "=r"((r)[13]), "=r"((r)[14]), "=r"((r)[15]), \
          "=r"((r)[16]), "=r"((r)[17]), "=r"((r)[18]), "=r"((r)[19]), \
          "=r"((r)[20]), "=r"((r)[21]), "=r"((r)[22]), "=r"((r)[23]), \
          "=r"((r)[24]), "=r"((r)[25]), "=r"((r)[26]), "=r"((r)[27]), \
          "=r"((r)[28]), "=r"((r)[29]), "=r"((r)[30]), "=r"((r)[31]) \
        : "r"(tmem_addr))
#endif // USE_TC5

// K-major SW128 descriptor (128B rows)
static __device__ constexpr uint64_t SMEM_DESC_BASE_SW128 =
    (uint64_t(2)  << 61) | (uint64_t(1) << 46) | (uint64_t(64) << 32) | (uint64_t(1) << 16);
#define MAKE_SMEM_DESC(base_addr) \
  (SMEM_DESC_BASE_SW128 | ((uint64_t)((base_addr) >> 4) & 0x3FFF))

// idesc: kind::f16, fp16 inputs, f32 accum, M=128, N=128
#define IDESC_F16 ((1u<<4) | ((BN/8)<<17) | ((BM/16)<<24))

#if USE_TC5
__device__ __forceinline__ void mma_f16_ss(uint32_t d, uint64_t ad, uint64_t bd,
                                           uint32_t idesc, bool acc){
  uint32_t en = acc ? 1u : 0u;
  asm volatile(
    "{\n\t.reg .pred p;\n\tsetp.ne.u32 p, %4, 0;\n\t"
    "tcgen05.mma.cta_group::1.kind::f16 [%0], %1, %2, %3, {%5, %5, %5, %5}, p;\n\t}"
    :: "r"(d), "l"(ad), "l"(bd), "r"(idesc), "r"(en), "r"(0u) : "memory");
}
#endif

// legacy fp16 tensor-core primitives (valid on base sm_80+ targets)
__device__ __forceinline__ void ldsm4(uint32_t* r, uint32_t addr){
  asm volatile("ldmatrix.sync.aligned.m8n8.x4.shared.b16 {%0,%1,%2,%3}, [%4];"
    : "=r"(r[0]),"=r"(r[1]),"=r"(r[2]),"=r"(r[3]) : "r"(addr));
}
__device__ __forceinline__ void mma16816(float* c, const uint32_t* a, const uint32_t* b){
  asm volatile("mma.sync.aligned.m16n8k16.row.col.f32.f16.f16.f32 "
    "{%0,%1,%2,%3}, {%4,%5,%6,%7}, {%8,%9}, {%0,%1,%2,%3};"
    : "+f"(c[0]),"+f"(c[1]),"+f"(c[2]),"+f"(c[3])
    : "r"(a[0]),"r"(a[1]),"r"(a[2]),"r"(a[3]),"r"(b[0]),"r"(b[1]));
}

__device__ __forceinline__ void cp16(uint32_t dst, const void* src){
  asm volatile("cp.async.cg.shared.global [%0], [%1], 16;" :: "r"(dst), "l"(src));
}
__device__ __forceinline__ void cp_commit(){ asm volatile("cp.async.commit_group;" ::: "memory"); }
template<int N> __device__ __forceinline__ void cp_wait(){
  asm volatile("cp.async.wait_group %0;" :: "n"(N) : "memory");
}

// ---------------- prep kernels ----------------
__global__ void zero_kernel(){
  int i = threadIdx.x;
  if (i < N_EXP) { g_counts[i]=0; g_cursor[i]=0; }
}

// transpose + fp32->fp16: src [Z][R][C] -> dst [Z][C][R]
__global__ void tconv_kernel(const float* __restrict__ src, __half* __restrict__ dst,
                             int R, int C){
  __shared__ float tile[32][33];
  size_t eoff = (size_t)blockIdx.z * R * C;
  int c  = blockIdx.x*32 + threadIdx.x;
  int r0 = blockIdx.y*32 + threadIdx.y;
  #pragma unroll
  for (int i=0;i<32;i+=8)
    tile[threadIdx.y+i][threadIdx.x] = src[eoff + (size_t)(r0+i)*C + c];
  __syncthreads();
  int rr = blockIdx.y*32 + threadIdx.x;
  int cc = blockIdx.x*32 + threadIdx.y;
  #pragma unroll
  for (int i=0;i<32;i+=8)
    dst[eoff + (size_t)(cc+i)*R + rr] = __float2half_rn(tile[threadIdx.x][threadIdx.y+i]);
}

__global__ void convh_kernel(const float* __restrict__ s, __half* __restrict__ d, long n){
  long i = ((long)blockIdx.x*blockDim.x + threadIdx.x)*4;
  if (i < n) {
    float4 v = *(const float4*)(s+i);
    __half2 a = __floats2half2_rn(v.x, v.y);
    __half2 b = __floats2half2_rn(v.z, v.w);
    ((__half2*)(d+i))[0] = a;
    ((__half2*)(d+i))[1] = b;
  }
}

// one warp per token: logits, softmax, top-4, shared sigmoid gate
__global__ void router_kernel(const float* __restrict__ X,
                              const float* __restrict__ RW,
                              const float* __restrict__ WGE){
  int warp = threadIdx.x >> 5, lane = threadIdx.x & 31;
  int t = blockIdx.x * 8 + warp;
  if (t >= T_TOK) return;
  const float* x = X + (size_t)t * H_DIM;
  float acc[N_EXP];
  #pragma unroll
  for (int e=0;e<N_EXP;e++) acc[e]=0.f;
  float accg = 0.f;
  for (int i4 = lane*4; i4 < H_DIM; i4 += 128) {
    float4 xv = *(const float4*)(x + i4);
    #pragma unroll
    for (int e=0;e<N_EXP;e++) {
      float4 wv = *(const float4*)(RW + (size_t)e*H_DIM + i4);
      acc[e] = fmaf(xv.x,wv.x,fmaf(xv.y,wv.y,fmaf(xv.z,wv.z,fmaf(xv.w,wv.w,acc[e]))));
    }
    float4 gv = *(const float4*)(WGE + i4);
    accg = fmaf(xv.x,gv.x,fmaf(xv.y,gv.y,fmaf(xv.z,gv.z,fmaf(xv.w,gv.w,accg))));
  }
  #pragma unroll
  for (int e=0;e<N_EXP;e++)
    #pragma unroll
    for (int o=16;o>0;o>>=1) acc[e] += __shfl_xor_sync(0xffffffffu, acc[e], o);
  #pragma unroll
  for (int o=16;o>0;o>>=1) accg += __shfl_xor_sync(0xffffffffu, accg, o);
  if (lane==0) {
    float m = acc[0];
    #pragma unroll
    for (int e=1;e<N_EXP;e++) m = fmaxf(m, acc[e]);
    float p[N_EXP]; float s=0.f;
    #pragma unroll
    for (int e=0;e<N_EXP;e++){ p[e]=expf(acc[e]-m); s+=p[e]; }
    float inv = 1.f/s;
    #pragma unroll
    for (int e=0;e<N_EXP;e++) p[e]*=inv;
    for (int k=0;k<K_SEL;k++){
      int be=0; float bv=-1.f;
      #pragma unroll
      for (int e=0;e<N_EXP;e++) if (p[e]>bv){bv=p[e];be=e;}
      g_route_w[t*K_SEL+k]=bv;
      g_route_e[t*K_SEL+k]=be;
      atomicAdd(&g_counts[be],1);
      p[be]=-2.f;
    }
    g_gate_s[t] = 1.f/(1.f+expf(-accg));
  }
}

__global__ void scan_kernel(){
  if (threadIdx.x==0) {
    int run=0, trun=0;
    for (int e=0;e<N_EXP;e++){
      g_offsets[e]=run; g_tile_off[e]=trun;
      run  += g_counts[e];
      trun += (g_counts[e]+BM-1)/BM;
    }
    g_tile_off[N_EXP]=trun;
    g_total_tiles=trun;
  }
}

__global__ void assign_kernel(){
  int id = blockIdx.x*blockDim.x + threadIdx.x;
  if (id >= TK) return;
  int e = g_route_e[id];
  int p = g_offsets[e] + atomicAdd(&g_cursor[e],1);
  g_row_token[p] = id >> 2;
  g_pos_of[id] = p;
}

// ---------------- tensor-core grouped/dense GEMM ----------------
// A: fp16 rows, K contiguous.  B: fp16 [N,K] rows (pre-transposed weights).
// DUAL: out = fp16 silu(D0)*D1.  else: fp32 store, or fp32 gated +=.
template<bool DUAL, bool GATHER, bool GADD>
__global__ __launch_bounds__(256) void tc_gemm(
    const __half* __restrict__ A,
    const __half* __restrict__ B0g,
    const __half* __restrict__ B1g,
    void* __restrict__ outp,
    int Kdim, long estride, int ldo,
    int grouped, int denseM,
    const float* __restrict__ gate_vec)
{
  int seg_start, seg, row0, e;
  if (grouped) {
    int w = blockIdx.y;
    if (w >= g_total_tiles) return;
    e = 0;
    while (w >= g_tile_off[e+1]) e++;
    seg_start = g_offsets[e]; seg = g_counts[e];
    row0 = (w - g_tile_off[e]) * BM;
  } else {
    e=0; seg_start=0; seg=denseM; row0 = blockIdx.y*BM;
  }
  if (row0 >= seg) return;
  int n0 = blockIdx.x * BN;

  extern __shared__ __align__(1024) char smem[];
  uint32_t sb = smem_to_u32(smem);
  const int STG = DUAL ? 49152 : 32768;   // A(16K)+B0(16K)(+B1 16K)
  const uint32_t st0 = sb + 1024;

  int tid = threadIdx.x;
  int wid = tid >> 5, lane = tid & 31;

  // load decomposition: thread -> (row rbase+32j, 16B chunk ch)
  int ch = tid & 7;
  int rbase = tid >> 3;   // 0..31
  const char* arow[4];
  const char* brow0[4];
  const char* brow1[4];
  const __half* B0e = B0g + (size_t)e * estride;
  const __half* B1e = DUAL ? (B1g + (size_t)e * estride) : (const __half*)nullptr;
  #pragma unroll
  for (int j=0;j<4;j++){
    int r = rbase + 32*j;
    int ar = row0 + r; if (ar >= seg) ar = seg-1;
    if (GATHER) arow[j] = (const char*)(A + (size_t)g_row_token[seg_start+ar]*Kdim);
    else        arow[j] = (const char*)(A + (size_t)(seg_start+ar)*Kdim);
    brow0[j] = (const char*)(B0e + (size_t)(n0 + r)*Kdim);
    if (DUAL) brow1[j] = (const char*)(B1e + (size_t)(n0 + r)*Kdim);
  }

  auto load_stage = [&](int kt2, int bufi){
    uint32_t base = st0 + bufi*STG;
    size_t koff = (size_t)kt2*BK2*2 + ch*16;
    #pragma unroll
    for (int j=0;j<4;j++){
      int r = rbase + 32*j;
      uint32_t sw = (uint32_t)((ch ^ (r & 7)) * 16);
      cp16(base + r*128 + sw,           arow[j]  + koff);
      cp16(base + 16384 + r*128 + sw,   brow0[j] + koff);
      if (DUAL) cp16(base + 32768 + r*128 + sw, brow1[j] + koff);
    }
    cp_commit();
  };

  int nk = Kdim / BK2;

#if USE_TC5
  // ================= tcgen05 path (sm_103a/f) =================
  if (tid == 0) { MBARRIER_INIT(sb+8, 1); MBARRIER_INIT(sb+16, 1); }
  if (wid == 0) { TCGEN05_ALLOC(sb, DUAL ? 256 : 128); TCGEN05_RELINQ(); }
  __syncthreads();
  uint32_t tmem;
  asm volatile("ld.shared.b32 %0, [%1];" : "=r"(tmem) : "r"(sb));

  int ph0 = 0, ph1 = 0;
  load_stage(0, 0);

  for (int kt=0; kt<nk; kt++){
    int buf = kt & 1;
    cp_wait<0>();
    asm volatile("fence.proxy.async.shared::cta;" ::: "memory");
    __syncthreads();
    if (wid == 0) {
      if (elect_one_pred()) {
        uint32_t base = st0 + buf*STG;
        uint64_t ad  = MAKE_SMEM_DESC(base);
        uint64_t bd0 = MAKE_SMEM_DESC(base + 16384);
        #pragma unroll
        for (int ks=0; ks<4; ks++)
          mma_f16_ss(tmem, ad + ks*2, bd0 + ks*2, IDESC_F16, (kt>0)||(ks>0));
        if (DUAL) {
          uint64_t bd1 = MAKE_SMEM_DESC(base + 32768);
          #pragma unroll
          for (int ks=0; ks<4; ks++)
            mma_f16_ss(tmem+128, ad + ks*2, bd1 + ks*2, IDESC_F16, (kt>0)||(ks>0));
        }
        TCGEN05_COMMIT(sb + 8 + 8*buf);
      }
    }
    if (kt+1 < nk) {
      int nb = buf ^ 1;
      if (kt >= 1) {
        if (nb==0){ MBARRIER_WAIT_PARITY(sb+8,  ph0); ph0^=1; }
        else      { MBARRIER_WAIT_PARITY(sb+16, ph1); ph1^=1; }
      }
      load_stage(kt+1, nb);
    }
  }
  { int lb = (nk-1)&1;
    if (lb==0){ MBARRIER_WAIT_PARITY(sb+8,  ph0); }
    else      { MBARRIER_WAIT_PARITY(sb+16, ph1); } }
  TCGEN05_FENCE_AFTER();

  if (tid < 128) {
    int r = wid*32 + lane;
    int rloc = row0 + r;
    bool valid = (rloc < seg);
    size_t orow = (size_t)(seg_start + rloc) * ldo + n0;
    #pragma unroll
    for (int cb=0; cb<4; cb++){
      uint32_t d0[32];
      TCGEN05_LD_32X32B_X32(d0, tmem + cb*32);
      if (DUAL) {
        uint32_t d1[32];
        TCGEN05_LD_32X32B_X32(d1, tmem + 128 + cb*32);
        TCGEN05_WAIT_LD();
        if (valid) {
          __half h[32];
          #pragma unroll
          for (int i=0;i<32;i++){
            float g = __uint_as_float(d0[i]);
            float u = __uint_as_float(d1[i]);
            float v = g * u / (1.f + __expf(-g));
            h[i] = __float2half_rn(v);
          }
          __half* dst = ((__half*)outp) + orow + cb*32;
          #pragma unroll
          for (int q=0;q<4;q++)
            *(uint4*)(dst + q*8) = *(const uint4*)(h + q*8);
        }
      } else {
        TCGEN05_WAIT_LD();
        if (valid) {
          float* dst = ((float*)outp) + orow + cb*32;
          if (GADD) {
            float gg = gate_vec[seg_start + rloc];
            #pragma unroll
            for (int q=0;q<8;q++){
              float4 cur = *(float4*)(dst + q*4);
              cur.x += gg*__uint_as_float(d0[q*4+0]);
              cur.y += gg*__uint_as_float(d0[q*4+1]);
              cur.z += gg*__uint_as_float(d0[q*4+2]);
              cur.w += gg*__uint_as_float(d0[q*4+3]);
              *(float4*)(dst + q*4) = cur;
            }
          } else {
            #pragma unroll
            for (int q=0;q<8;q++){
              float4 v;
              v.x = __uint_as_float(d0[q*4+0]);
              v.y = __uint_as_float(d0[q*4+1]);
              v.z = __uint_as_float(d0[q*4+2]);
              v.w = __uint_as_float(d0[q*4+3]);
              *(float4*)(dst + q*4) = v;
            }
          }
        }
      }
    }
    TCGEN05_FENCE_BEFORE();
  }
  __syncthreads();
  if (tid == 0) { MBARRIER_INVAL(sb+8); MBARRIER_INVAL(sb+16); }
  if (wid == 0) { TCGEN05_DEALLOC(tmem, DUAL ? 256 : 128); }

#else
  // ============ legacy mma.sync fp16 path (base sm_103) ============
  // warp grid 4x2: warp covers rows [wm*32,+32), cols [wn*64,+64)
  int wm = wid & 3;
  int wn = wid >> 2;

  float acc0[2][8][4];
  float acc1[DUAL?2:1][DUAL?8:1][DUAL?4:1];
  #pragma unroll
  for (int mt=0;mt<2;mt++)
    #pragma unroll
    for (int nt=0;nt<8;nt++)
      #pragma unroll
      for (int q=0;q<4;q++){ acc0[mt][nt][q]=0.f; if (DUAL) acc1[mt][nt][q]=0.f; }

  load_stage(0, 0);

  for (int kt=0; kt<nk; kt++){
    int buf = kt & 1;
    if (kt+1 < nk) { load_stage(kt+1, buf^1); cp_wait<1>(); }
    else           { cp_wait<0>(); }
    __syncthreads();
    uint32_t base = st0 + buf*STG;
    #pragma unroll
    for (int ks=0; ks<4; ks++){
      // A fragments: two m16 tiles
      uint32_t afr[2][4];
      #pragma unroll
      for (int mt=0;mt<2;mt++){
        int r = wm*32 + mt*16 + (lane & 15);
        int chunk = 2*ks + (lane >> 4);
        uint32_t addr = base + r*128 + (uint32_t)((chunk ^ (r & 7)) << 4);
        ldsm4(afr[mt], addr);
      }
      #pragma unroll
      for (int jp=0; jp<4; jp++){
        int nrow = wn*64 + jp*16 + ((lane >> 4) & 1)*8 + (lane & 7);
        int chunk = 2*ks + ((lane >> 3) & 1);
        uint32_t sw = (uint32_t)((chunk ^ (nrow & 7)) << 4);
        uint32_t bfr[4];
        ldsm4(bfr, base + 16384 + nrow*128 + sw);
        #pragma unroll
        for (int mt=0;mt<2;mt++){
          mma16816(acc0[mt][jp*2+0], afr[mt], bfr+0);
          mma16816(acc0[mt][jp*2+1], afr[mt], bfr+2);
        }
        if (DUAL) {
          uint32_t cfr[4];
          ldsm4(cfr, base + 32768 + nrow*128 + sw);
          #pragma unroll
          for (int mt=0;mt<2;mt++){
            mma16816(acc1[mt][jp*2+0], afr[mt], cfr+0);
            mma16816(acc1[mt][jp*2+1], afr[mt], cfr+2);
          }
        }
      }
    }
    __syncthreads();
  }

  // ---- epilogue from registers ----
  int tr  = lane >> 2;         // 0..7
  int tc2 = (lane & 3) * 2;    // 0,2,4,6
  #pragma unroll
  for (int mt=0;mt<2;mt++){
    #pragma unroll
    for (int half=0; half<2; half++){
      int rloc = row0 + wm*32 + mt*16 + tr + half*8;
      if (rloc < seg) {
        size_t orow = (size_t)(seg_start + rloc) * ldo + n0 + wn*64;
        float gg = GADD ? gate_vec[seg_start + rloc] : 0.f;
        #pragma unroll
        for (int nt=0; nt<8; nt++){
          int cc = nt*8 + tc2;
          float v0 = acc0[mt][nt][half*2+0];
          float v1 = acc0[mt][nt][half*2+1];
          if (DUAL) {
            float u0 = acc1[mt][nt][half*2+0];
            float u1 = acc1[mt][nt][half*2+1];
            float w0 = v0 * u0 / (1.f + __expf(-v0));
            float w1 = v1 * u1 / (1.f + __expf(-v1));
            *(__half2*)(((__half*)outp) + orow + cc) = __floats2half2_rn(w0, w1);
          } else if (GADD) {
            float* dst = ((float*)outp) + orow + cc;
            float2 cur = *(float2*)dst;
            cur.x += gg*v0; cur.y += gg*v1;
            *(float2*)dst = cur;
          } else {
            float* dst = ((float*)outp) + orow + cc;
            float2 st; st.x = v0; st.y = v1;
            *(float2*)dst = st;
          }
        }
      }
    }
  }
#endif
}

// out[t,:] = sum_k w[t,k] * replica[pos[t,k], :]
__global__ void combine_kernel(float* __restrict__ out){
  int id = blockIdx.x*blockDim.x + threadIdx.x;
  const int HV = H_DIM/4;
  if (id >= T_TOK*HV) return;
  int t  = id / HV;
  int h4 = (id % HV) * 4;
  float4 acc = make_float4(0.f,0.f,0.f,0.f);
  #pragma unroll
  for (int k=0;k<K_SEL;k++){
    float w = g_route_w[t*K_SEL+k];
    int   p = g_pos_of[t*K_SEL+k];
    float4 v = *(const float4*)&g_replica[(size_t)p*H_DIM + h4];
    acc.x = fmaf(w, v.x, acc.x);
    acc.y = fmaf(w, v.y, acc.y);
    acc.z = fmaf(w, v.z, acc.z);
    acc.w = fmaf(w, v.w, acc.w);
  }
  *(float4*)&out[(size_t)t*H_DIM + h4] = acc;
}

// ---------------- launch ----------------
extern "C" void kernel_launch(void* const* d_in, const int* in_sizes, int n_in,
                              void* d_out, int out_size) {
  const float* X   = (const float*)d_in[0];
  const float* RW  = (const float*)d_in[1];
  const float* GUW = (const float*)d_in[2];
  const float* DW  = (const float*)d_in[3];
  const float* SGW = (const float*)d_in[4];
  const float* SUW = (const float*)d_in[5];
  const float* SDW = (const float*)d_in[6];
  const float* WGE = (const float*)d_in[7];
  float* out = (float*)d_out;

  void *pv;
  cudaGetSymbolAddress(&pv, g_x16);    __half* p_x16  = (__half*)pv;
  cudaGetSymbolAddress(&pv, g_guwt);   __half* p_guwt = (__half*)pv;
  cudaGetSymbolAddress(&pv, g_dwt);    __half* p_dwt  = (__half*)pv;
  cudaGetSymbolAddress(&pv, g_sgwt);   __half* p_sgwt = (__half*)pv;
  cudaGetSymbolAddress(&pv, g_suwt);   __half* p_suwt = (__half*)pv;
  cudaGetSymbolAddress(&pv, g_sdwt);   __half* p_sdwt = (__half*)pv;
  cudaGetSymbolAddress(&pv, g_act);    __half* p_act  = (__half*)pv;
  cudaGetSymbolAddress(&pv, g_s1);     __half* p_s1   = (__half*)pv;
  cudaGetSymbolAddress(&pv, g_replica);float*  p_rep  = (float*)pv;
  cudaGetSymbolAddress(&pv, g_gate_s); float*  p_gate = (float*)pv;

  const int SMEM_DUAL   = 1024 + 2*49152;
  const int SMEM_SINGLE = 1024 + 2*32768;
  cudaFuncSetAttribute(tc_gemm<true,true,false>,  cudaFuncAttributeMaxDynamicSharedMemorySize, SMEM_DUAL);
  cudaFuncSetAttribute(tc_gemm<true,false,false>, cudaFuncAttributeMaxDynamicSharedMemorySize, SMEM_DUAL);
  cudaFuncSetAttribute(tc_gemm<false,false,false>,cudaFuncAttributeMaxDynamicSharedMemorySize, SMEM_SINGLE);
  cudaFuncSetAttribute(tc_gemm<false,false,true>, cudaFuncAttributeMaxDynamicSharedMemorySize, SMEM_SINGLE);

  dim3 tb(32,8);
  zero_kernel<<<1,32>>>();
  // weight transposes + fp16 conversion
  tconv_kernel<<<dim3(2*IM/32, H_DIM/32, N_EXP), tb>>>(GUW, p_guwt, H_DIM, 2*IM);
  tconv_kernel<<<dim3(H_DIM/32, IM/32,   N_EXP), tb>>>(DW,  p_dwt,  IM,    H_DIM);
  tconv_kernel<<<dim3(ISH/32,   H_DIM/32, 1),    tb>>>(SGW, p_sgwt, H_DIM, ISH);
  tconv_kernel<<<dim3(ISH/32,   H_DIM/32, 1),    tb>>>(SUW, p_suwt, H_DIM, ISH);
  tconv_kernel<<<dim3(H_DIM/32, ISH/32,   1),    tb>>>(SDW, p_sdwt, ISH,   H_DIM);
  convh_kernel<<<(long)T_TOK*H_DIM/4/256, 256>>>(X, p_x16, (long)T_TOK*H_DIM);

  router_kernel<<<T_TOK/8,256>>>(X, RW, WGE);
  scan_kernel<<<1,32>>>();
  assign_kernel<<<TK/256,256>>>();

  // G1: act = silu(Xg @ Wgate) * (Xg @ Wup)   (grouped, gathered rows, fp16 out)
  tc_gemm<true,true,false><<<dim3(IM/BN, MAX_GTILES), 256, SMEM_DUAL>>>(
      p_x16, p_guwt, p_guwt + (size_t)IM*H_DIM, p_act,
      H_DIM, (long)2*IM*H_DIM, IM, 1, 0, nullptr);

  // G2: replica = act @ down_w[e]   (grouped, fp32 out)
  tc_gemm<false,false,false><<<dim3(H_DIM/BN, MAX_GTILES), 256, SMEM_SINGLE>>>(
      p_act, p_dwt, nullptr, p_rep,
      IM, (long)H_DIM*IM, H_DIM, 1, 0, nullptr);

  combine_kernel<<<(T_TOK*(H_DIM/4))/256,256>>>(out);

  // G3: s1 = silu(X @ Wsg) * (X @ Wsu)   (dense, fp16 out)
  tc_gemm<true,false,false><<<dim3(ISH/BN, T_TOK/BM), 256, SMEM_DUAL>>>(
      p_x16, p_sgwt, p_suwt, p_s1,
      H_DIM, 0, ISH, 0, T_TOK, nullptr);

  // G4: out += sigmoid_gate * (s1 @ Wsd)   (dense, fp32 gated accumulate)
  tc_gemm<false,false,true><<<dim3(H_DIM/BN, T_TOK/BM), 256, SMEM_SINGLE>>>(
      p_s1, p_sdwt, nullptr, out,
      ISH, 0, H_DIM, 0, T_TOK, p_gate);
}